// round 9
// baseline (speedup 1.0000x reference)
#include <cuda_runtime.h>
#include <cuda_fp16.h>
#include <math.h>
#include <stdint.h>

#define NB 32
#define C  512
#define S  3136   // 56*56
#define S4 (S/4)  // 784
#define S8 (S/8)  // 392
#define BK 32
#define NCHUNK (S / BK)   // 98

// ---------------- scratch (device globals; no allocations allowed) ----------------
__device__ __half g_eh[(size_t)NB * C * S];   // fp16(4096 * exp(7*(x - rowmax)))
__device__ __half g_xh[(size_t)NB * C * S];   // fp16(x)
__device__ float g_invZ[NB * C];              // 1 / sum(e')
__device__ float g_B[(size_t)NB * C * C];     // raw bilinear logits (pre-softmax)
__device__ float g_w[NB * C];                 // w[n,d] = sum_c softmax(B)[c,d]

__device__ __forceinline__ uint32_t smem_u32(const void* p) {
    uint32_t a;
    asm("{ .reg .u64 t; cvta.to.shared.u64 t, %1; cvt.u32.u64 %0, t; }" : "=r"(a) : "l"(p));
    return a;
}

// ---------------- block reductions ----------------
__device__ __forceinline__ float blockReduceMax(float v) {
    __shared__ float sh[32];
    int lane = threadIdx.x & 31, w = threadIdx.x >> 5;
    __syncthreads();
    #pragma unroll
    for (int o = 16; o; o >>= 1) v = fmaxf(v, __shfl_xor_sync(0xffffffffu, v, o));
    if (lane == 0) sh[w] = v;
    __syncthreads();
    int nw = (blockDim.x + 31) >> 5;
    if (w == 0) {
        v = (lane < nw) ? sh[lane] : -INFINITY;
        #pragma unroll
        for (int o = 16; o; o >>= 1) v = fmaxf(v, __shfl_xor_sync(0xffffffffu, v, o));
        if (lane == 0) sh[0] = v;
    }
    __syncthreads();
    return sh[0];
}
__device__ __forceinline__ float blockReduceSum(float v) {
    __shared__ float sh[32];
    int lane = threadIdx.x & 31, w = threadIdx.x >> 5;
    __syncthreads();
    #pragma unroll
    for (int o = 16; o; o >>= 1) v += __shfl_xor_sync(0xffffffffu, v, o);
    if (lane == 0) sh[w] = v;
    __syncthreads();
    int nw = (blockDim.x + 31) >> 5;
    if (w == 0) {
        v = (lane < nw) ? sh[lane] : 0.0f;
        #pragma unroll
        for (int o = 16; o; o >>= 1) v += __shfl_xor_sync(0xffffffffu, v, o);
        if (lane == 0) sh[0] = v;
    }
    __syncthreads();
    return sh[0];
}

__device__ __forceinline__ uint2 pack4(float a, float b, float c, float d) {
    __half2 h0 = __floats2half2_rn(a, b);
    __half2 h1 = __floats2half2_rn(c, d);
    uint2 o;
    o.x = *(uint32_t*)&h0;
    o.y = *(uint32_t*)&h1;
    return o;
}

// ---------------- kernel 1: rowmax + scaled exp -> fp16; x -> fp16.
// Row held in registers: 256 threads x up-to-4 float4 slots. One global read.
__global__ __launch_bounds__(256) void k_rowexp(const float* __restrict__ x) {
    const size_t row = blockIdx.x;  // n*C + c
    const float4* xr = (const float4*)(x + row * S);
    uint2* er = (uint2*)(g_eh + row * S);
    uint2* hr = (uint2*)(g_xh + row * S);
    const int t = threadIdx.x;

    // S4 = 784 = 3*256 + 16
    float4 v0 = xr[t];
    float4 v1 = xr[t + 256];
    float4 v2 = xr[t + 512];
    float4 v3 = (t < 16) ? xr[t + 768]
                         : make_float4(-INFINITY, -INFINITY, -INFINITY, -INFINITY);

    float m = fmaxf(fmaxf(v0.x, v0.y), fmaxf(v0.z, v0.w));
    m = fmaxf(m, fmaxf(fmaxf(v1.x, v1.y), fmaxf(v1.z, v1.w)));
    m = fmaxf(m, fmaxf(fmaxf(v2.x, v2.y), fmaxf(v2.z, v2.w)));
    m = fmaxf(m, fmaxf(fmaxf(v3.x, v3.y), fmaxf(v3.z, v3.w)));
    m = blockReduceMax(m);

    const float k = 10.098865286222744f;  // 7/ln(2)
    float s = 0.0f;

    {   // slot 0
        hr[t] = pack4(v0.x, v0.y, v0.z, v0.w);
        float e0 = exp2f(fmaf(k, v0.x - m, 12.0f));
        float e1 = exp2f(fmaf(k, v0.y - m, 12.0f));
        float e2 = exp2f(fmaf(k, v0.z - m, 12.0f));
        float e3 = exp2f(fmaf(k, v0.w - m, 12.0f));
        s += (e0 + e1) + (e2 + e3);
        er[t] = pack4(e0, e1, e2, e3);
    }
    {   // slot 1
        hr[t + 256] = pack4(v1.x, v1.y, v1.z, v1.w);
        float e0 = exp2f(fmaf(k, v1.x - m, 12.0f));
        float e1 = exp2f(fmaf(k, v1.y - m, 12.0f));
        float e2 = exp2f(fmaf(k, v1.z - m, 12.0f));
        float e3 = exp2f(fmaf(k, v1.w - m, 12.0f));
        s += (e0 + e1) + (e2 + e3);
        er[t + 256] = pack4(e0, e1, e2, e3);
    }
    {   // slot 2
        hr[t + 512] = pack4(v2.x, v2.y, v2.z, v2.w);
        float e0 = exp2f(fmaf(k, v2.x - m, 12.0f));
        float e1 = exp2f(fmaf(k, v2.y - m, 12.0f));
        float e2 = exp2f(fmaf(k, v2.z - m, 12.0f));
        float e3 = exp2f(fmaf(k, v2.w - m, 12.0f));
        s += (e0 + e1) + (e2 + e3);
        er[t + 512] = pack4(e0, e1, e2, e3);
    }
    if (t < 16) {   // slot 3
        hr[t + 768] = pack4(v3.x, v3.y, v3.z, v3.w);
        float e0 = exp2f(fmaf(k, v3.x - m, 12.0f));
        float e1 = exp2f(fmaf(k, v3.y - m, 12.0f));
        float e2 = exp2f(fmaf(k, v3.z - m, 12.0f));
        float e3 = exp2f(fmaf(k, v3.w - m, 12.0f));
        s += (e0 + e1) + (e2 + e3);
        er[t + 768] = pack4(e0, e1, e2, e3);
    }
    s = blockReduceSum(s);
    if (t == 0) g_invZ[row] = 1.0f / s;
}

// ---------------- kernel 2: warp-MMA batched GEMM  B[n] = E[n] @ Xh[n]^T ----------------
#define LDA 40
#define TILE_B (128 * LDA * 2)        // 10240 bytes per tile
#define STAGE_B (2 * TILE_B)          // A, B
#define NSTAGE 3
#define SMEM_TOTAL (NSTAGE * STAGE_B) // 61440

__device__ __forceinline__ void cp16(uint32_t saddr, const void* gptr) {
    asm volatile("cp.async.cg.shared.global [%0], [%1], 16;" :: "r"(saddr), "l"(gptr) : "memory");
}

__global__ __launch_bounds__(256) void k_gemm_mma() {
    extern __shared__ __align__(16) unsigned char sm[];

    const int tid = threadIdx.x, lane = tid & 31, wid = tid >> 5;
    const int n = blockIdx.z, tm = blockIdx.y, tn = blockIdx.x;
    const int wm = wid >> 1, wn = wid & 1;   // warp tile: rows wm*32, cols wn*64

    const size_t nb = (size_t)n * C * S;
    const int lr = tid >> 1;             // 0..127
    const int lc = (tid & 1) * 16;       // 0 or 16 (elems)
    const __half* Aptr = g_eh + nb + (size_t)(tm * 128 + lr) * S + lc;
    const __half* Xptr = g_xh + nb + (size_t)(tn * 128 + lr) * S + lc;
    const uint32_t sRow = (uint32_t)(lr * (LDA * 2) + lc * 2);
    const uint32_t smBase = smem_u32(sm);

    const int q = lane >> 3, r8 = lane & 7;
    const uint32_t laneOff = (uint32_t)((((q & 1) << 3) + r8) * (LDA * 2) + ((q >> 1) << 3) * 2);

    float acc[2][8][4];
    #pragma unroll
    for (int mi = 0; mi < 2; mi++)
        #pragma unroll
        for (int ni = 0; ni < 8; ni++)
            #pragma unroll
            for (int j = 0; j < 4; j++) acc[mi][ni][j] = 0.0f;

    auto issue = [&](int it) {
        const int buf = it % NSTAGE;
        const int k0 = it * BK;
        const uint32_t sa = smBase + (uint32_t)buf * STAGE_B + sRow;
        const __half* ga = Aptr + k0;
        const __half* gx = Xptr + k0;
        cp16(sa, ga);                   cp16(sa + 16, ga + 8);
        cp16(sa + TILE_B, gx);          cp16(sa + TILE_B + 16, gx + 8);
        asm volatile("cp.async.commit_group;" ::: "memory");
    };

    issue(0);
    issue(1);

    for (int it = 0; it < NCHUNK; it++) {
        if (it + 1 < NCHUNK) {
            asm volatile("cp.async.wait_group 1;" ::: "memory");
        } else {
            asm volatile("cp.async.wait_group 0;" ::: "memory");
        }
        __syncthreads();
        if (it + 2 < NCHUNK) issue(it + 2);

        const int buf = it % NSTAGE;
        const uint32_t base = smBase + (uint32_t)buf * STAGE_B;
        const uint32_t aB = base + (uint32_t)(wm * 32) * (LDA * 2) + laneOff;
        const uint32_t bB = base + TILE_B + (uint32_t)(wn * 64) * (LDA * 2) + laneOff;

        #pragma unroll
        for (int kk = 0; kk < 2; kk++) {
            uint32_t a[2][4], bh[4][4];
            #pragma unroll
            for (int mi = 0; mi < 2; mi++) {
                asm volatile("ldmatrix.sync.aligned.m8n8.x4.shared.b16 {%0,%1,%2,%3}, [%4];"
                    : "=r"(a[mi][0]), "=r"(a[mi][1]), "=r"(a[mi][2]), "=r"(a[mi][3])
                    : "r"(aB + (uint32_t)(mi * 16) * (LDA * 2) + (uint32_t)kk * 32));
            }
            #pragma unroll
            for (int p = 0; p < 4; p++) {
                asm volatile("ldmatrix.sync.aligned.m8n8.x4.shared.b16 {%0,%1,%2,%3}, [%4];"
                    : "=r"(bh[p][0]), "=r"(bh[p][1]), "=r"(bh[p][2]), "=r"(bh[p][3])
                    : "r"(bB + (uint32_t)(p * 16) * (LDA * 2) + (uint32_t)kk * 32));
            }
            #pragma unroll
            for (int mi = 0; mi < 2; mi++) {
                #pragma unroll
                for (int p = 0; p < 4; p++) {
                    asm volatile(
                        "mma.sync.aligned.m16n8k16.row.col.f32.f16.f16.f32 "
                        "{%0,%1,%2,%3},{%4,%5,%6,%7},{%8,%9},{%0,%1,%2,%3};"
                        : "+f"(acc[mi][2*p][0]), "+f"(acc[mi][2*p][1]),
                          "+f"(acc[mi][2*p][2]), "+f"(acc[mi][2*p][3])
                        : "r"(a[mi][0]), "r"(a[mi][1]), "r"(a[mi][2]), "r"(a[mi][3]),
                          "r"(bh[p][0]), "r"(bh[p][2]));
                    asm volatile(
                        "mma.sync.aligned.m16n8k16.row.col.f32.f16.f16.f32 "
                        "{%0,%1,%2,%3},{%4,%5,%6,%7},{%8,%9},{%0,%1,%2,%3};"
                        : "+f"(acc[mi][2*p+1][0]), "+f"(acc[mi][2*p+1][1]),
                          "+f"(acc[mi][2*p+1][2]), "+f"(acc[mi][2*p+1][3])
                        : "r"(a[mi][0]), "r"(a[mi][1]), "r"(a[mi][2]), "r"(a[mi][3]),
                          "r"(bh[p][1]), "r"(bh[p][3]));
                }
            }
        }
    }

    // epilogue: acc -> g_B
    float* Cn = g_B + (size_t)n * C * C;
    const int mrow0 = tm * 128 + wm * 32 + (lane >> 2);
    const int ncol0 = tn * 128 + wn * 64 + (lane & 3) * 2;
    #pragma unroll
    for (int mi = 0; mi < 2; mi++) {
        #pragma unroll
        for (int ni = 0; ni < 8; ni++) {
            const int r = mrow0 + mi * 16;
            const int cc = ncol0 + ni * 8;
            *(float2*)&Cn[(size_t)r * C + cc]       = make_float2(acc[mi][ni][0], acc[mi][ni][1]);
            *(float2*)&Cn[(size_t)(r + 8) * C + cc] = make_float2(acc[mi][ni][2], acc[mi][ni][3]);
        }
    }
}

// ---------------- kernel z: zero g_w ----------------
__global__ void k_zero() {
    g_w[blockIdx.x * 1024 + threadIdx.x] = 0.0f;
}

// ---------------- kernel 3: fused row-softmax + column-sum ----------------
// grid (NB, 8): CTA = 64 rows of batch n. Warp per row (8 rows/warp).
__global__ void k_bsm() {
    __shared__ float cac[8][C];   // 16 KB
    const int n = blockIdx.x, cb = blockIdx.y;
    const int lane = threadIdx.x & 31, wid = threadIdx.x >> 5;

    float wacc[4][4];
    #pragma unroll
    for (int q = 0; q < 4; q++)
        #pragma unroll
        for (int j = 0; j < 4; j++) wacc[q][j] = 0.0f;

    for (int r = wid; r < 64; r += 8) {
        const int row = cb * 64 + r;
        const float* Br = g_B + (size_t)n * C * C + (size_t)row * C;
        const float iz = g_invZ[n * C + row];
        float4 v[4];
        float m = -INFINITY;
        #pragma unroll
        for (int q = 0; q < 4; q++) {
            v[q] = *(const float4*)(Br + q * 128 + lane * 4);
            v[q].x *= iz; v[q].y *= iz; v[q].z *= iz; v[q].w *= iz;
            m = fmaxf(m, fmaxf(fmaxf(v[q].x, v[q].y), fmaxf(v[q].z, v[q].w)));
        }
        #pragma unroll
        for (int o = 16; o; o >>= 1) m = fmaxf(m, __shfl_xor_sync(0xffffffffu, m, o));
        float s = 0.0f;
        #pragma unroll
        for (int q = 0; q < 4; q++) {
            v[q].x = __expf(v[q].x - m); v[q].y = __expf(v[q].y - m);
            v[q].z = __expf(v[q].z - m); v[q].w = __expf(v[q].w - m);
            s += (v[q].x + v[q].y) + (v[q].z + v[q].w);
        }
        #pragma unroll
        for (int o = 16; o; o >>= 1) s += __shfl_xor_sync(0xffffffffu, s, o);
        const float inv = 1.0f / s;
        #pragma unroll
        for (int q = 0; q < 4; q++) {
            wacc[q][0] = fmaf(v[q].x, inv, wacc[q][0]);
            wacc[q][1] = fmaf(v[q].y, inv, wacc[q][1]);
            wacc[q][2] = fmaf(v[q].z, inv, wacc[q][2]);
            wacc[q][3] = fmaf(v[q].w, inv, wacc[q][3]);
        }
    }
    #pragma unroll
    for (int q = 0; q < 4; q++)
        *(float4*)&cac[wid][q * 128 + lane * 4] =
            make_float4(wacc[q][0], wacc[q][1], wacc[q][2], wacc[q][3]);
    __syncthreads();
    #pragma unroll
    for (int h = 0; h < 2; h++) {
        const int col = threadIdx.x + h * 256;
        float s = 0.0f;
        #pragma unroll
        for (int w = 0; w < 8; w++) s += cac[w][col];
        atomicAdd(&g_w[n * C + col], s);
    }
}

// ---------------- kernel 4: out[n, p*8..p*8+7] = sum_d w[n,d] * xh[n,d,...] ----------------
// uint4 loads (8 halves), dual accumulator chains, MLP ~8.
__global__ __launch_bounds__(128) void k_out(float* __restrict__ out) {
    const int n = blockIdx.y;
    const int p = blockIdx.x * 128 + threadIdx.x;   // 0..511 (S8=392 valid)
    __shared__ float ws[C];
    for (int i = threadIdx.x; i < C; i += 128) ws[i] = g_w[n * C + i];
    __syncthreads();
    if (p >= S8) return;
    const uint4* fb = (const uint4*)(g_xh + (size_t)n * C * S) + p;   // row stride S8 uint4

    float a[8], b[8];
    #pragma unroll
    for (int j = 0; j < 8; j++) { a[j] = 0.0f; b[j] = 0.0f; }

    #pragma unroll 4
    for (int d = 0; d < C; d += 2) {
        uint4 v0 = fb[(size_t)d * S8];
        uint4 v1 = fb[(size_t)(d + 1) * S8];
        const float w0 = ws[d], w1 = ws[d + 1];
        float2 f;
        f = __half22float2(*(__half2*)&v0.x); a[0] = fmaf(w0, f.x, a[0]); a[1] = fmaf(w0, f.y, a[1]);
        f = __half22float2(*(__half2*)&v0.y); a[2] = fmaf(w0, f.x, a[2]); a[3] = fmaf(w0, f.y, a[3]);
        f = __half22float2(*(__half2*)&v0.z); a[4] = fmaf(w0, f.x, a[4]); a[5] = fmaf(w0, f.y, a[5]);
        f = __half22float2(*(__half2*)&v0.w); a[6] = fmaf(w0, f.x, a[6]); a[7] = fmaf(w0, f.y, a[7]);
        f = __half22float2(*(__half2*)&v1.x); b[0] = fmaf(w1, f.x, b[0]); b[1] = fmaf(w1, f.y, b[1]);
        f = __half22float2(*(__half2*)&v1.y); b[2] = fmaf(w1, f.x, b[2]); b[3] = fmaf(w1, f.y, b[3]);
        f = __half22float2(*(__half2*)&v1.z); b[4] = fmaf(w1, f.x, b[4]); b[5] = fmaf(w1, f.y, b[5]);
        f = __half22float2(*(__half2*)&v1.w); b[6] = fmaf(w1, f.x, b[6]); b[7] = fmaf(w1, f.y, b[7]);
    }

    float* o = out + (size_t)n * S + (size_t)p * 8;
    *(float4*)o       = make_float4(a[0] + b[0], a[1] + b[1], a[2] + b[2], a[3] + b[3]);
    *(float4*)(o + 4) = make_float4(a[4] + b[4], a[5] + b[5], a[6] + b[6], a[7] + b[7]);
}

extern "C" void kernel_launch(void* const* d_in, const int* in_sizes, int n_in,
                              void* d_out, int out_size) {
    const float* x = (const float*)d_in[0];
    float* out = (float*)d_out;

    cudaFuncSetAttribute(k_gemm_mma, cudaFuncAttributeMaxDynamicSharedMemorySize, SMEM_TOTAL);

    k_rowexp<<<NB * C, 256>>>(x);

    dim3 g2(C / 128, C / 128, NB);   // (4,4,32) = 512 CTAs
    k_gemm_mma<<<g2, 256, SMEM_TOTAL>>>();

    k_zero<<<NB * C / 1024, 1024>>>();   // 16 blocks

    dim3 g3(NB, 8);                  // (32,8) = 256 CTAs
    k_bsm<<<g3, 256>>>();

    dim3 g4(4, NB);                  // (4,32)
    k_out<<<g4, 128>>>(out);
}

// round 10
// speedup vs baseline: 1.1081x; 1.1081x over previous
#include <cuda_runtime.h>
#include <cuda_fp16.h>
#include <math.h>
#include <stdint.h>

#define NB 32
#define C  512
#define S  3136   // 56*56
#define S4 (S/4)
#define BK 32
#define NCHUNK (S / BK)   // 98

// ---------------- scratch (device globals; no allocations allowed) ----------------
__device__ __half g_eh[(size_t)NB * C * S];   // fp16(4096 * exp(7*(x - rowmax)))
__device__ __half g_xh[(size_t)NB * C * S];   // fp16(x)
__device__ float g_invZ[NB * C];              // 1 / sum(e')
__device__ float g_B[(size_t)NB * C * C];     // raw bilinear logits (pre-softmax)
__device__ float g_w[NB * C];                 // w[n,d] = sum_c softmax(B)[c,d]

__device__ __forceinline__ uint32_t smem_u32(const void* p) {
    uint32_t a;
    asm("{ .reg .u64 t; cvta.to.shared.u64 t, %1; cvt.u32.u64 %0, t; }" : "=r"(a) : "l"(p));
    return a;
}

// ---------------- block reductions ----------------
__device__ __forceinline__ float blockReduceMax(float v) {
    __shared__ float sh[32];
    int lane = threadIdx.x & 31, w = threadIdx.x >> 5;
    __syncthreads();
    #pragma unroll
    for (int o = 16; o; o >>= 1) v = fmaxf(v, __shfl_xor_sync(0xffffffffu, v, o));
    if (lane == 0) sh[w] = v;
    __syncthreads();
    int nw = (blockDim.x + 31) >> 5;
    if (w == 0) {
        v = (lane < nw) ? sh[lane] : -INFINITY;
        #pragma unroll
        for (int o = 16; o; o >>= 1) v = fmaxf(v, __shfl_xor_sync(0xffffffffu, v, o));
        if (lane == 0) sh[0] = v;
    }
    __syncthreads();
    return sh[0];
}
__device__ __forceinline__ float blockReduceSum(float v) {
    __shared__ float sh[32];
    int lane = threadIdx.x & 31, w = threadIdx.x >> 5;
    __syncthreads();
    #pragma unroll
    for (int o = 16; o; o >>= 1) v += __shfl_xor_sync(0xffffffffu, v, o);
    if (lane == 0) sh[w] = v;
    __syncthreads();
    int nw = (blockDim.x + 31) >> 5;
    if (w == 0) {
        v = (lane < nw) ? sh[lane] : 0.0f;
        #pragma unroll
        for (int o = 16; o; o >>= 1) v += __shfl_xor_sync(0xffffffffu, v, o);
        if (lane == 0) sh[0] = v;
    }
    __syncthreads();
    return sh[0];
}

// ---------------- kernel 1: rowmax + scaled exp -> fp16; x -> fp16. Single global read via SMEM cache.
__global__ void k_rowexp(const float* __restrict__ x) {
    __shared__ __align__(16) float xs[S];   // 12.5 KB row cache
    size_t row = blockIdx.x;  // n*C + c
    const float4* xr = (const float4*)(x + row * S);
    float4* xs4 = (float4*)xs;
    uint2* er = (uint2*)(g_eh + row * S);   // 4 halves per uint2
    uint2* hr = (uint2*)(g_xh + row * S);

    float m = -INFINITY;
    for (int i = threadIdx.x; i < S4; i += blockDim.x) {
        float4 v = xr[i];
        xs4[i] = v;
        m = fmaxf(m, fmaxf(fmaxf(v.x, v.y), fmaxf(v.z, v.w)));
    }
    m = blockReduceMax(m);

    const float k = 10.098865286222744f;  // 7/ln(2)
    float s = 0.0f;
    for (int i = threadIdx.x; i < S4; i += blockDim.x) {
        float4 v = xs4[i];
        __half2 x01 = __halves2half2(__float2half_rn(v.x), __float2half_rn(v.y));
        __half2 x23 = __halves2half2(__float2half_rn(v.z), __float2half_rn(v.w));
        uint2 ho;
        ho.x = *(uint32_t*)&x01;
        ho.y = *(uint32_t*)&x23;
        hr[i] = ho;
        float e0 = exp2f(fmaf(k, v.x - m, 12.0f));   // 4096 * exp(7*(x-m))
        float e1 = exp2f(fmaf(k, v.y - m, 12.0f));
        float e2 = exp2f(fmaf(k, v.z - m, 12.0f));
        float e3 = exp2f(fmaf(k, v.w - m, 12.0f));
        s += (e0 + e1) + (e2 + e3);
        __half2 h01 = __halves2half2(__float2half_rn(e0), __float2half_rn(e1));
        __half2 h23 = __halves2half2(__float2half_rn(e2), __float2half_rn(e3));
        uint2 o;
        o.x = *(uint32_t*)&h01;
        o.y = *(uint32_t*)&h23;
        er[i] = o;
    }
    s = blockReduceSum(s);
    if (threadIdx.x == 0) g_invZ[row] = 1.0f / s;
}

// ---------------- kernel 2: warp-MMA batched GEMM  B[n] = E[n] @ Xh[n]^T ----------------
#define LDA 40
#define TILE_B (128 * LDA * 2)        // 10240 bytes per tile
#define STAGE_B (2 * TILE_B)          // A, B
#define NSTAGE 3
#define SMEM_TOTAL (NSTAGE * STAGE_B) // 61440

__device__ __forceinline__ void cp16(uint32_t saddr, const void* gptr) {
    asm volatile("cp.async.cg.shared.global [%0], [%1], 16;" :: "r"(saddr), "l"(gptr) : "memory");
}

__global__ __launch_bounds__(256) void k_gemm_mma() {
    extern __shared__ __align__(16) unsigned char sm[];

    const int tid = threadIdx.x, lane = tid & 31, wid = tid >> 5;
    const int n = blockIdx.z, tm = blockIdx.y, tn = blockIdx.x;
    const int wm = wid >> 1, wn = wid & 1;   // warp tile: rows wm*32, cols wn*64

    const size_t nb = (size_t)n * C * S;
    const int lr = tid >> 1;             // 0..127
    const int lc = (tid & 1) * 16;       // 0 or 16 (elems)
    const __half* Aptr = g_eh + nb + (size_t)(tm * 128 + lr) * S + lc;
    const __half* Xptr = g_xh + nb + (size_t)(tn * 128 + lr) * S + lc;
    const uint32_t sRow = (uint32_t)(lr * (LDA * 2) + lc * 2);
    const uint32_t smBase = smem_u32(sm);

    const int q = lane >> 3, r8 = lane & 7;
    const uint32_t laneOff = (uint32_t)((((q & 1) << 3) + r8) * (LDA * 2) + ((q >> 1) << 3) * 2);

    float acc[2][8][4];
    #pragma unroll
    for (int mi = 0; mi < 2; mi++)
        #pragma unroll
        for (int ni = 0; ni < 8; ni++)
            #pragma unroll
            for (int j = 0; j < 4; j++) acc[mi][ni][j] = 0.0f;

    auto issue = [&](int it) {
        const int buf = it % NSTAGE;
        const int k0 = it * BK;
        const uint32_t sa = smBase + (uint32_t)buf * STAGE_B + sRow;
        const __half* ga = Aptr + k0;
        const __half* gx = Xptr + k0;
        cp16(sa, ga);                   cp16(sa + 16, ga + 8);
        cp16(sa + TILE_B, gx);          cp16(sa + TILE_B + 16, gx + 8);
        asm volatile("cp.async.commit_group;" ::: "memory");
    };

    issue(0);
    issue(1);

    for (int it = 0; it < NCHUNK; it++) {
        if (it + 1 < NCHUNK) {
            asm volatile("cp.async.wait_group 1;" ::: "memory");
        } else {
            asm volatile("cp.async.wait_group 0;" ::: "memory");
        }
        __syncthreads();
        if (it + 2 < NCHUNK) issue(it + 2);

        const int buf = it % NSTAGE;
        const uint32_t base = smBase + (uint32_t)buf * STAGE_B;
        const uint32_t aB = base + (uint32_t)(wm * 32) * (LDA * 2) + laneOff;
        const uint32_t bB = base + TILE_B + (uint32_t)(wn * 64) * (LDA * 2) + laneOff;

        #pragma unroll
        for (int kk = 0; kk < 2; kk++) {
            uint32_t a[2][4], bh[4][4];
            #pragma unroll
            for (int mi = 0; mi < 2; mi++) {
                asm volatile("ldmatrix.sync.aligned.m8n8.x4.shared.b16 {%0,%1,%2,%3}, [%4];"
                    : "=r"(a[mi][0]), "=r"(a[mi][1]), "=r"(a[mi][2]), "=r"(a[mi][3])
                    : "r"(aB + (uint32_t)(mi * 16) * (LDA * 2) + (uint32_t)kk * 32));
            }
            #pragma unroll
            for (int p = 0; p < 4; p++) {
                asm volatile("ldmatrix.sync.aligned.m8n8.x4.shared.b16 {%0,%1,%2,%3}, [%4];"
                    : "=r"(bh[p][0]), "=r"(bh[p][1]), "=r"(bh[p][2]), "=r"(bh[p][3])
                    : "r"(bB + (uint32_t)(p * 16) * (LDA * 2) + (uint32_t)kk * 32));
            }
            #pragma unroll
            for (int mi = 0; mi < 2; mi++) {
                #pragma unroll
                for (int p = 0; p < 4; p++) {
                    asm volatile(
                        "mma.sync.aligned.m16n8k16.row.col.f32.f16.f16.f32 "
                        "{%0,%1,%2,%3},{%4,%5,%6,%7},{%8,%9},{%0,%1,%2,%3};"
                        : "+f"(acc[mi][2*p][0]), "+f"(acc[mi][2*p][1]),
                          "+f"(acc[mi][2*p][2]), "+f"(acc[mi][2*p][3])
                        : "r"(a[mi][0]), "r"(a[mi][1]), "r"(a[mi][2]), "r"(a[mi][3]),
                          "r"(bh[p][0]), "r"(bh[p][2]));
                    asm volatile(
                        "mma.sync.aligned.m16n8k16.row.col.f32.f16.f16.f32 "
                        "{%0,%1,%2,%3},{%4,%5,%6,%7},{%8,%9},{%0,%1,%2,%3};"
                        : "+f"(acc[mi][2*p+1][0]), "+f"(acc[mi][2*p+1][1]),
                          "+f"(acc[mi][2*p+1][2]), "+f"(acc[mi][2*p+1][3])
                        : "r"(a[mi][0]), "r"(a[mi][1]), "r"(a[mi][2]), "r"(a[mi][3]),
                          "r"(bh[p][1]), "r"(bh[p][3]));
                }
            }
        }
    }

    // epilogue: acc -> g_B
    float* Cn = g_B + (size_t)n * C * C;
    const int mrow0 = tm * 128 + wm * 32 + (lane >> 2);
    const int ncol0 = tn * 128 + wn * 64 + (lane & 3) * 2;
    #pragma unroll
    for (int mi = 0; mi < 2; mi++) {
        #pragma unroll
        for (int ni = 0; ni < 8; ni++) {
            const int r = mrow0 + mi * 16;
            const int cc = ncol0 + ni * 8;
            *(float2*)&Cn[(size_t)r * C + cc]       = make_float2(acc[mi][ni][0], acc[mi][ni][1]);
            *(float2*)&Cn[(size_t)(r + 8) * C + cc] = make_float2(acc[mi][ni][2], acc[mi][ni][3]);
        }
    }
}

// ---------------- kernel z: zero g_w ----------------
__global__ void k_zero() {
    g_w[blockIdx.x * 1024 + threadIdx.x] = 0.0f;
}

// ---------------- kernel 3: fused row-softmax + column-sum ----------------
// grid (NB, 8): CTA = 64 rows of batch n. Warp per row (8 rows/warp).
__global__ void k_bsm() {
    __shared__ float cac[8][C];   // 16 KB
    const int n = blockIdx.x, cb = blockIdx.y;
    const int lane = threadIdx.x & 31, wid = threadIdx.x >> 5;

    float wacc[4][4];
    #pragma unroll
    for (int q = 0; q < 4; q++)
        #pragma unroll
        for (int j = 0; j < 4; j++) wacc[q][j] = 0.0f;

    for (int r = wid; r < 64; r += 8) {
        const int row = cb * 64 + r;
        const float* Br = g_B + (size_t)n * C * C + (size_t)row * C;
        const float iz = g_invZ[n * C + row];
        float4 v[4];
        float m = -INFINITY;
        #pragma unroll
        for (int q = 0; q < 4; q++) {
            v[q] = *(const float4*)(Br + q * 128 + lane * 4);
            v[q].x *= iz; v[q].y *= iz; v[q].z *= iz; v[q].w *= iz;
            m = fmaxf(m, fmaxf(fmaxf(v[q].x, v[q].y), fmaxf(v[q].z, v[q].w)));
        }
        #pragma unroll
        for (int o = 16; o; o >>= 1) m = fmaxf(m, __shfl_xor_sync(0xffffffffu, m, o));
        float s = 0.0f;
        #pragma unroll
        for (int q = 0; q < 4; q++) {
            v[q].x = __expf(v[q].x - m); v[q].y = __expf(v[q].y - m);
            v[q].z = __expf(v[q].z - m); v[q].w = __expf(v[q].w - m);
            s += (v[q].x + v[q].y) + (v[q].z + v[q].w);
        }
        #pragma unroll
        for (int o = 16; o; o >>= 1) s += __shfl_xor_sync(0xffffffffu, s, o);
        const float inv = 1.0f / s;
        #pragma unroll
        for (int q = 0; q < 4; q++) {
            wacc[q][0] = fmaf(v[q].x, inv, wacc[q][0]);
            wacc[q][1] = fmaf(v[q].y, inv, wacc[q][1]);
            wacc[q][2] = fmaf(v[q].z, inv, wacc[q][2]);
            wacc[q][3] = fmaf(v[q].w, inv, wacc[q][3]);
        }
    }
    #pragma unroll
    for (int q = 0; q < 4; q++)
        *(float4*)&cac[wid][q * 128 + lane * 4] =
            make_float4(wacc[q][0], wacc[q][1], wacc[q][2], wacc[q][3]);
    __syncthreads();
    #pragma unroll
    for (int h = 0; h < 2; h++) {
        const int col = threadIdx.x + h * 256;
        float s = 0.0f;
        #pragma unroll
        for (int w = 0; w < 8; w++) s += cac[w][col];
        atomicAdd(&g_w[n * C + col], s);
    }
}

// ---------------- kernel 4: out[n,2s..2s+1] = sum_d w[n,d] * xh[n,d,2s..2s+1] ----------------
#define S2 (S / 2)   // 1568 half2 per row
__global__ void k_out(float* __restrict__ out) {
    int n = blockIdx.y;
    int s2 = blockIdx.x * 256 + threadIdx.x;
    __shared__ float ws[C];
    for (int i = threadIdx.x; i < C; i += 256) ws[i] = g_w[n * C + i];
    __syncthreads();
    if (s2 >= S2) return;
    const __half2* fb = (const __half2*)(g_xh + (size_t)n * C * S) + s2;
    float a0 = 0, a1 = 0, b0 = 0, b1 = 0;
    #pragma unroll 4
    for (int d = 0; d < C; d += 2) {
        float2 f0 = __half22float2(fb[(size_t)d * S2]);
        float2 f1 = __half22float2(fb[(size_t)(d + 1) * S2]);
        a0 = fmaf(ws[d], f0.x, a0);
        a1 = fmaf(ws[d], f0.y, a1);
        b0 = fmaf(ws[d + 1], f1.x, b0);
        b1 = fmaf(ws[d + 1], f1.y, b1);
    }
    float2* o = (float2*)(out + (size_t)n * S) + s2;
    *o = make_float2(a0 + b0, a1 + b1);
}

extern "C" void kernel_launch(void* const* d_in, const int* in_sizes, int n_in,
                              void* d_out, int out_size) {
    const float* x = (const float*)d_in[0];
    float* out = (float*)d_out;

    cudaFuncSetAttribute(k_gemm_mma, cudaFuncAttributeMaxDynamicSharedMemorySize, SMEM_TOTAL);

    k_rowexp<<<NB * C, 256>>>(x);

    dim3 g2(C / 128, C / 128, NB);   // (4,4,32) = 512 CTAs
    k_gemm_mma<<<g2, 256, SMEM_TOTAL>>>();

    k_zero<<<NB * C / 1024, 1024>>>();   // 16 blocks

    dim3 g3(NB, 8);                  // (32,8) = 256 CTAs
    k_bsm<<<g3, 256>>>();

    dim3 g4((S2 + 255) / 256, NB);   // (7,32)
    k_out<<<g4, 256>>>(out);
}

// round 11
// speedup vs baseline: 1.1190x; 1.0098x over previous
#include <cuda_runtime.h>
#include <cuda_fp16.h>
#include <math.h>
#include <stdint.h>

#define NB 32
#define C  512
#define S  3136   // 56*56
#define S4 (S/4)
#define BK 32
#define NCHUNK (S / BK)   // 98

// ---------------- scratch (device globals; no allocations allowed) ----------------
__device__ __half g_eh[(size_t)NB * C * S];   // fp16(4096 * exp(7*(x - rowmax)))
__device__ __half g_xh[(size_t)NB * C * S];   // fp16(x)
__device__ float g_invZ[NB * C];              // 1 / sum(e')
__device__ float g_B[(size_t)NB * C * C];     // raw bilinear logits (pre-softmax)
__device__ float g_wpart[8][NB * C];          // partial column sums of softmax(B)

__device__ __forceinline__ uint32_t smem_u32(const void* p) {
    uint32_t a;
    asm("{ .reg .u64 t; cvta.to.shared.u64 t, %1; cvt.u32.u64 %0, t; }" : "=r"(a) : "l"(p));
    return a;
}

// ---------------- block reductions ----------------
__device__ __forceinline__ float blockReduceMax(float v) {
    __shared__ float sh[32];
    int lane = threadIdx.x & 31, w = threadIdx.x >> 5;
    __syncthreads();
    #pragma unroll
    for (int o = 16; o; o >>= 1) v = fmaxf(v, __shfl_xor_sync(0xffffffffu, v, o));
    if (lane == 0) sh[w] = v;
    __syncthreads();
    int nw = (blockDim.x + 31) >> 5;
    if (w == 0) {
        v = (lane < nw) ? sh[lane] : -INFINITY;
        #pragma unroll
        for (int o = 16; o; o >>= 1) v = fmaxf(v, __shfl_xor_sync(0xffffffffu, v, o));
        if (lane == 0) sh[0] = v;
    }
    __syncthreads();
    return sh[0];
}
__device__ __forceinline__ float blockReduceSum(float v) {
    __shared__ float sh[32];
    int lane = threadIdx.x & 31, w = threadIdx.x >> 5;
    __syncthreads();
    #pragma unroll
    for (int o = 16; o; o >>= 1) v += __shfl_xor_sync(0xffffffffu, v, o);
    if (lane == 0) sh[w] = v;
    __syncthreads();
    int nw = (blockDim.x + 31) >> 5;
    if (w == 0) {
        v = (lane < nw) ? sh[lane] : 0.0f;
        #pragma unroll
        for (int o = 16; o; o >>= 1) v += __shfl_xor_sync(0xffffffffu, v, o);
        if (lane == 0) sh[0] = v;
    }
    __syncthreads();
    return sh[0];
}

// ---------------- kernel 1: rowmax + scaled exp -> fp16; x -> fp16. Single global read via SMEM cache.
__global__ void k_rowexp(const float* __restrict__ x) {
    __shared__ __align__(16) float xs[S];   // 12.5 KB row cache
    size_t row = blockIdx.x;  // n*C + c
    const float4* xr = (const float4*)(x + row * S);
    float4* xs4 = (float4*)xs;
    uint2* er = (uint2*)(g_eh + row * S);   // 4 halves per uint2
    uint2* hr = (uint2*)(g_xh + row * S);

    float m = -INFINITY;
    for (int i = threadIdx.x; i < S4; i += blockDim.x) {
        float4 v = xr[i];
        xs4[i] = v;
        m = fmaxf(m, fmaxf(fmaxf(v.x, v.y), fmaxf(v.z, v.w)));
    }
    m = blockReduceMax(m);

    const float k = 10.098865286222744f;  // 7/ln(2)
    float s = 0.0f;
    for (int i = threadIdx.x; i < S4; i += blockDim.x) {
        float4 v = xs4[i];
        __half2 x01 = __halves2half2(__float2half_rn(v.x), __float2half_rn(v.y));
        __half2 x23 = __halves2half2(__float2half_rn(v.z), __float2half_rn(v.w));
        uint2 ho;
        ho.x = *(uint32_t*)&x01;
        ho.y = *(uint32_t*)&x23;
        hr[i] = ho;
        float e0 = exp2f(fmaf(k, v.x - m, 12.0f));   // 4096 * exp(7*(x-m))
        float e1 = exp2f(fmaf(k, v.y - m, 12.0f));
        float e2 = exp2f(fmaf(k, v.z - m, 12.0f));
        float e3 = exp2f(fmaf(k, v.w - m, 12.0f));
        s += (e0 + e1) + (e2 + e3);
        __half2 h01 = __halves2half2(__float2half_rn(e0), __float2half_rn(e1));
        __half2 h23 = __halves2half2(__float2half_rn(e2), __float2half_rn(e3));
        uint2 o;
        o.x = *(uint32_t*)&h01;
        o.y = *(uint32_t*)&h23;
        er[i] = o;
    }
    s = blockReduceSum(s);
    if (threadIdx.x == 0) g_invZ[row] = 1.0f / s;
}

// ---------------- kernel 2: warp-MMA batched GEMM  B[n] = E[n] @ Xh[n]^T ----------------
// 2-stage cp.async pipeline (40KB SMEM -> 4-5 CTAs/SM -> single wave for 512 CTAs).
#define LDA 40
#define TILE_B (128 * LDA * 2)        // 10240 bytes per tile
#define STAGE_B (2 * TILE_B)          // A, B
#define NSTAGE 2
#define SMEM_TOTAL (NSTAGE * STAGE_B) // 40960

__device__ __forceinline__ void cp16(uint32_t saddr, const void* gptr) {
    asm volatile("cp.async.cg.shared.global [%0], [%1], 16;" :: "r"(saddr), "l"(gptr) : "memory");
}

__global__ __launch_bounds__(256) void k_gemm_mma() {
    extern __shared__ __align__(16) unsigned char sm[];

    const int tid = threadIdx.x, lane = tid & 31, wid = tid >> 5;
    const int n = blockIdx.z, tm = blockIdx.y, tn = blockIdx.x;
    const int wm = wid >> 1, wn = wid & 1;   // warp tile: rows wm*32, cols wn*64

    const size_t nb = (size_t)n * C * S;
    const int lr = tid >> 1;             // 0..127
    const int lc = (tid & 1) * 16;       // 0 or 16 (elems)
    const __half* Aptr = g_eh + nb + (size_t)(tm * 128 + lr) * S + lc;
    const __half* Xptr = g_xh + nb + (size_t)(tn * 128 + lr) * S + lc;
    const uint32_t sRow = (uint32_t)(lr * (LDA * 2) + lc * 2);
    const uint32_t smBase = smem_u32(sm);

    const int q = lane >> 3, r8 = lane & 7;
    const uint32_t laneOff = (uint32_t)((((q & 1) << 3) + r8) * (LDA * 2) + ((q >> 1) << 3) * 2);

    float acc[2][8][4];
    #pragma unroll
    for (int mi = 0; mi < 2; mi++)
        #pragma unroll
        for (int ni = 0; ni < 8; ni++)
            #pragma unroll
            for (int j = 0; j < 4; j++) acc[mi][ni][j] = 0.0f;

    auto issue = [&](int it) {
        const int buf = it & 1;
        const int k0 = it * BK;
        const uint32_t sa = smBase + (uint32_t)buf * STAGE_B + sRow;
        const __half* ga = Aptr + k0;
        const __half* gx = Xptr + k0;
        cp16(sa, ga);                   cp16(sa + 16, ga + 8);
        cp16(sa + TILE_B, gx);          cp16(sa + TILE_B + 16, gx + 8);
        asm volatile("cp.async.commit_group;" ::: "memory");
    };

    issue(0);

    for (int it = 0; it < NCHUNK; it++) {
        if (it + 1 < NCHUNK) {
            issue(it + 1);
            asm volatile("cp.async.wait_group 1;" ::: "memory");
        } else {
            asm volatile("cp.async.wait_group 0;" ::: "memory");
        }
        __syncthreads();

        const int buf = it & 1;
        const uint32_t base = smBase + (uint32_t)buf * STAGE_B;
        const uint32_t aB = base + (uint32_t)(wm * 32) * (LDA * 2) + laneOff;
        const uint32_t bB = base + TILE_B + (uint32_t)(wn * 64) * (LDA * 2) + laneOff;

        #pragma unroll
        for (int kk = 0; kk < 2; kk++) {
            uint32_t a[2][4], bh[4][4];
            #pragma unroll
            for (int mi = 0; mi < 2; mi++) {
                asm volatile("ldmatrix.sync.aligned.m8n8.x4.shared.b16 {%0,%1,%2,%3}, [%4];"
                    : "=r"(a[mi][0]), "=r"(a[mi][1]), "=r"(a[mi][2]), "=r"(a[mi][3])
                    : "r"(aB + (uint32_t)(mi * 16) * (LDA * 2) + (uint32_t)kk * 32));
            }
            #pragma unroll
            for (int p = 0; p < 4; p++) {
                asm volatile("ldmatrix.sync.aligned.m8n8.x4.shared.b16 {%0,%1,%2,%3}, [%4];"
                    : "=r"(bh[p][0]), "=r"(bh[p][1]), "=r"(bh[p][2]), "=r"(bh[p][3])
                    : "r"(bB + (uint32_t)(p * 16) * (LDA * 2) + (uint32_t)kk * 32));
            }
            #pragma unroll
            for (int mi = 0; mi < 2; mi++) {
                #pragma unroll
                for (int p = 0; p < 4; p++) {
                    asm volatile(
                        "mma.sync.aligned.m16n8k16.row.col.f32.f16.f16.f32 "
                        "{%0,%1,%2,%3},{%4,%5,%6,%7},{%8,%9},{%0,%1,%2,%3};"
                        : "+f"(acc[mi][2*p][0]), "+f"(acc[mi][2*p][1]),
                          "+f"(acc[mi][2*p][2]), "+f"(acc[mi][2*p][3])
                        : "r"(a[mi][0]), "r"(a[mi][1]), "r"(a[mi][2]), "r"(a[mi][3]),
                          "r"(bh[p][0]), "r"(bh[p][2]));
                    asm volatile(
                        "mma.sync.aligned.m16n8k16.row.col.f32.f16.f16.f32 "
                        "{%0,%1,%2,%3},{%4,%5,%6,%7},{%8,%9},{%0,%1,%2,%3};"
                        : "+f"(acc[mi][2*p+1][0]), "+f"(acc[mi][2*p+1][1]),
                          "+f"(acc[mi][2*p+1][2]), "+f"(acc[mi][2*p+1][3])
                        : "r"(a[mi][0]), "r"(a[mi][1]), "r"(a[mi][2]), "r"(a[mi][3]),
                          "r"(bh[p][1]), "r"(bh[p][3]));
                }
            }
        }
        __syncthreads();   // protect buf before it+2 overwrites it
    }

    // epilogue: acc -> g_B
    float* Cn = g_B + (size_t)n * C * C;
    const int mrow0 = tm * 128 + wm * 32 + (lane >> 2);
    const int ncol0 = tn * 128 + wn * 64 + (lane & 3) * 2;
    #pragma unroll
    for (int mi = 0; mi < 2; mi++) {
        #pragma unroll
        for (int ni = 0; ni < 8; ni++) {
            const int r = mrow0 + mi * 16;
            const int cc = ncol0 + ni * 8;
            *(float2*)&Cn[(size_t)r * C + cc]       = make_float2(acc[mi][ni][0], acc[mi][ni][1]);
            *(float2*)&Cn[(size_t)(r + 8) * C + cc] = make_float2(acc[mi][ni][2], acc[mi][ni][3]);
        }
    }
}

// ---------------- kernel 3: fused row-softmax + partial column-sum ----------------
// grid (NB, 8): CTA = 64 rows of batch n. Warp per row (8 rows/warp).
// Writes partial slab g_wpart[cb] with plain stores (no atomics, no zero-init).
__global__ void k_bsm() {
    __shared__ float cac[8][C];   // 16 KB
    const int n = blockIdx.x, cb = blockIdx.y;
    const int lane = threadIdx.x & 31, wid = threadIdx.x >> 5;

    float wacc[4][4];
    #pragma unroll
    for (int q = 0; q < 4; q++)
        #pragma unroll
        for (int j = 0; j < 4; j++) wacc[q][j] = 0.0f;

    for (int r = wid; r < 64; r += 8) {
        const int row = cb * 64 + r;
        const float* Br = g_B + (size_t)n * C * C + (size_t)row * C;
        const float iz = g_invZ[n * C + row];
        float4 v[4];
        float m = -INFINITY;
        #pragma unroll
        for (int q = 0; q < 4; q++) {
            v[q] = *(const float4*)(Br + q * 128 + lane * 4);
            v[q].x *= iz; v[q].y *= iz; v[q].z *= iz; v[q].w *= iz;
            m = fmaxf(m, fmaxf(fmaxf(v[q].x, v[q].y), fmaxf(v[q].z, v[q].w)));
        }
        #pragma unroll
        for (int o = 16; o; o >>= 1) m = fmaxf(m, __shfl_xor_sync(0xffffffffu, m, o));
        float s = 0.0f;
        #pragma unroll
        for (int q = 0; q < 4; q++) {
            v[q].x = __expf(v[q].x - m); v[q].y = __expf(v[q].y - m);
            v[q].z = __expf(v[q].z - m); v[q].w = __expf(v[q].w - m);
            s += (v[q].x + v[q].y) + (v[q].z + v[q].w);
        }
        #pragma unroll
        for (int o = 16; o; o >>= 1) s += __shfl_xor_sync(0xffffffffu, s, o);
        const float inv = 1.0f / s;
        #pragma unroll
        for (int q = 0; q < 4; q++) {
            wacc[q][0] = fmaf(v[q].x, inv, wacc[q][0]);
            wacc[q][1] = fmaf(v[q].y, inv, wacc[q][1]);
            wacc[q][2] = fmaf(v[q].z, inv, wacc[q][2]);
            wacc[q][3] = fmaf(v[q].w, inv, wacc[q][3]);
        }
    }
    #pragma unroll
    for (int q = 0; q < 4; q++)
        *(float4*)&cac[wid][q * 128 + lane * 4] =
            make_float4(wacc[q][0], wacc[q][1], wacc[q][2], wacc[q][3]);
    __syncthreads();
    #pragma unroll
    for (int h = 0; h < 2; h++) {
        const int col = threadIdx.x + h * 256;
        float s = 0.0f;
        #pragma unroll
        for (int w = 0; w < 8; w++) s += cac[w][col];
        g_wpart[cb][n * C + col] = s;
    }
}

// ---------------- kernel 4: out[n,2s..2s+1] = sum_d w[n,d] * xh[n,d,2s..2s+1] ----------------
#define S2 (S / 2)   // 1568 half2 per row
__global__ void k_out(float* __restrict__ out) {
    int n = blockIdx.y;
    int s2 = blockIdx.x * 256 + threadIdx.x;
    __shared__ float ws[C];
    for (int i = threadIdx.x; i < C; i += 256) {
        float s = 0.0f;
        #pragma unroll
        for (int w = 0; w < 8; w++) s += g_wpart[w][n * C + i];
        ws[i] = s;
    }
    __syncthreads();
    if (s2 >= S2) return;
    const __half2* fb = (const __half2*)(g_xh + (size_t)n * C * S) + s2;
    float a0 = 0, a1 = 0, b0 = 0, b1 = 0;
    #pragma unroll 4
    for (int d = 0; d < C; d += 2) {
        float2 f0 = __half22float2(fb[(size_t)d * S2]);
        float2 f1 = __half22float2(fb[(size_t)(d + 1) * S2]);
        a0 = fmaf(ws[d], f0.x, a0);
        a1 = fmaf(ws[d], f0.y, a1);
        b0 = fmaf(ws[d + 1], f1.x, b0);
        b1 = fmaf(ws[d + 1], f1.y, b1);
    }
    float2* o = (float2*)(out + (size_t)n * S) + s2;
    *o = make_float2(a0 + b0, a1 + b1);
}

extern "C" void kernel_launch(void* const* d_in, const int* in_sizes, int n_in,
                              void* d_out, int out_size) {
    const float* x = (const float*)d_in[0];
    float* out = (float*)d_out;

    cudaFuncSetAttribute(k_gemm_mma, cudaFuncAttributeMaxDynamicSharedMemorySize, SMEM_TOTAL);

    k_rowexp<<<NB * C, 256>>>(x);

    dim3 g2(C / 128, C / 128, NB);   // (4,4,32) = 512 CTAs
    k_gemm_mma<<<g2, 256, SMEM_TOTAL>>>();

    dim3 g3(NB, 8);                  // (32,8) = 256 CTAs
    k_bsm<<<g3, 256>>>();

    dim3 g4((S2 + 255) / 256, NB);   // (7,32)
    k_out<<<g4, 256>>>(out);
}

// round 12
// speedup vs baseline: 1.1837x; 1.0579x over previous
#include <cuda_runtime.h>
#include <cuda_fp16.h>
#include <math.h>
#include <stdint.h>

#define NB 32
#define C  512
#define S  3136   // 56*56
#define S4 (S/4)
#define BK 32
#define NCHUNK (S / BK)   // 98

// ---------------- scratch (device globals; no allocations allowed) ----------------
__device__ __half g_eh[(size_t)NB * C * S];   // fp16(4096 * exp(7*(x - rowmax)))
__device__ __half g_xh[(size_t)NB * C * S];   // fp16(x)
__device__ float g_invZ[NB * C];              // 1 / sum(e')
__device__ float g_B[(size_t)NB * C * C];     // raw bilinear logits (pre-softmax)
__device__ float g_wpart[8][NB * C];          // partial column sums of softmax(B)
__device__ float g_opart[4][NB * S];          // partial output sums (d-split)

__device__ __forceinline__ uint32_t smem_u32(const void* p) {
    uint32_t a;
    asm("{ .reg .u64 t; cvta.to.shared.u64 t, %1; cvt.u32.u64 %0, t; }" : "=r"(a) : "l"(p));
    return a;
}

// ---------------- block reductions ----------------
__device__ __forceinline__ float blockReduceMax(float v) {
    __shared__ float sh[32];
    int lane = threadIdx.x & 31, w = threadIdx.x >> 5;
    __syncthreads();
    #pragma unroll
    for (int o = 16; o; o >>= 1) v = fmaxf(v, __shfl_xor_sync(0xffffffffu, v, o));
    if (lane == 0) sh[w] = v;
    __syncthreads();
    int nw = (blockDim.x + 31) >> 5;
    if (w == 0) {
        v = (lane < nw) ? sh[lane] : -INFINITY;
        #pragma unroll
        for (int o = 16; o; o >>= 1) v = fmaxf(v, __shfl_xor_sync(0xffffffffu, v, o));
        if (lane == 0) sh[0] = v;
    }
    __syncthreads();
    return sh[0];
}
__device__ __forceinline__ float blockReduceSum(float v) {
    __shared__ float sh[32];
    int lane = threadIdx.x & 31, w = threadIdx.x >> 5;
    __syncthreads();
    #pragma unroll
    for (int o = 16; o; o >>= 1) v += __shfl_xor_sync(0xffffffffu, v, o);
    if (lane == 0) sh[w] = v;
    __syncthreads();
    int nw = (blockDim.x + 31) >> 5;
    if (w == 0) {
        v = (lane < nw) ? sh[lane] : 0.0f;
        #pragma unroll
        for (int o = 16; o; o >>= 1) v += __shfl_xor_sync(0xffffffffu, v, o);
        if (lane == 0) sh[0] = v;
    }
    __syncthreads();
    return sh[0];
}

// ---------------- kernel 1: rowmax + scaled exp -> fp16; x -> fp16. Single global read via SMEM cache.
__global__ void k_rowexp(const float* __restrict__ x) {
    __shared__ __align__(16) float xs[S];   // 12.5 KB row cache
    size_t row = blockIdx.x;  // n*C + c
    const float4* xr = (const float4*)(x + row * S);
    float4* xs4 = (float4*)xs;
    uint2* er = (uint2*)(g_eh + row * S);   // 4 halves per uint2
    uint2* hr = (uint2*)(g_xh + row * S);

    float m = -INFINITY;
    for (int i = threadIdx.x; i < S4; i += blockDim.x) {
        float4 v = xr[i];
        xs4[i] = v;
        m = fmaxf(m, fmaxf(fmaxf(v.x, v.y), fmaxf(v.z, v.w)));
    }
    m = blockReduceMax(m);

    const float k = 10.098865286222744f;  // 7/ln(2)
    float s = 0.0f;
    for (int i = threadIdx.x; i < S4; i += blockDim.x) {
        float4 v = xs4[i];
        __half2 x01 = __halves2half2(__float2half_rn(v.x), __float2half_rn(v.y));
        __half2 x23 = __halves2half2(__float2half_rn(v.z), __float2half_rn(v.w));
        uint2 ho;
        ho.x = *(uint32_t*)&x01;
        ho.y = *(uint32_t*)&x23;
        hr[i] = ho;
        float e0 = exp2f(fmaf(k, v.x - m, 12.0f));   // 4096 * exp(7*(x-m))
        float e1 = exp2f(fmaf(k, v.y - m, 12.0f));
        float e2 = exp2f(fmaf(k, v.z - m, 12.0f));
        float e3 = exp2f(fmaf(k, v.w - m, 12.0f));
        s += (e0 + e1) + (e2 + e3);
        __half2 h01 = __halves2half2(__float2half_rn(e0), __float2half_rn(e1));
        __half2 h23 = __halves2half2(__float2half_rn(e2), __float2half_rn(e3));
        uint2 o;
        o.x = *(uint32_t*)&h01;
        o.y = *(uint32_t*)&h23;
        er[i] = o;
    }
    s = blockReduceSum(s);
    if (threadIdx.x == 0) g_invZ[row] = 1.0f / s;
}

// ---------------- kernel 2: warp-MMA batched GEMM  B[n] = E[n] @ Xh[n]^T ----------------
#define LDA 40
#define TILE_B (128 * LDA * 2)        // 10240 bytes per tile
#define STAGE_B (2 * TILE_B)          // A, B
#define NSTAGE 2
#define SMEM_TOTAL (NSTAGE * STAGE_B) // 40960

__device__ __forceinline__ void cp16(uint32_t saddr, const void* gptr) {
    asm volatile("cp.async.cg.shared.global [%0], [%1], 16;" :: "r"(saddr), "l"(gptr) : "memory");
}

__global__ __launch_bounds__(256) void k_gemm_mma() {
    extern __shared__ __align__(16) unsigned char sm[];

    const int tid = threadIdx.x, lane = tid & 31, wid = tid >> 5;
    const int n = blockIdx.z, tm = blockIdx.y, tn = blockIdx.x;
    const int wm = wid >> 1, wn = wid & 1;   // warp tile: rows wm*32, cols wn*64

    const size_t nb = (size_t)n * C * S;
    const int lr = tid >> 1;             // 0..127
    const int lc = (tid & 1) * 16;       // 0 or 16 (elems)
    const __half* Aptr = g_eh + nb + (size_t)(tm * 128 + lr) * S + lc;
    const __half* Xptr = g_xh + nb + (size_t)(tn * 128 + lr) * S + lc;
    const uint32_t sRow = (uint32_t)(lr * (LDA * 2) + lc * 2);
    const uint32_t smBase = smem_u32(sm);

    const int q = lane >> 3, r8 = lane & 7;
    const uint32_t laneOff = (uint32_t)((((q & 1) << 3) + r8) * (LDA * 2) + ((q >> 1) << 3) * 2);

    float acc[2][8][4];
    #pragma unroll
    for (int mi = 0; mi < 2; mi++)
        #pragma unroll
        for (int ni = 0; ni < 8; ni++)
            #pragma unroll
            for (int j = 0; j < 4; j++) acc[mi][ni][j] = 0.0f;

    auto issue = [&](int it) {
        const int buf = it & 1;
        const int k0 = it * BK;
        const uint32_t sa = smBase + (uint32_t)buf * STAGE_B + sRow;
        const __half* ga = Aptr + k0;
        const __half* gx = Xptr + k0;
        cp16(sa, ga);                   cp16(sa + 16, ga + 8);
        cp16(sa + TILE_B, gx);          cp16(sa + TILE_B + 16, gx + 8);
        asm volatile("cp.async.commit_group;" ::: "memory");
    };

    issue(0);

    for (int it = 0; it < NCHUNK; it++) {
        if (it + 1 < NCHUNK) {
            issue(it + 1);
            asm volatile("cp.async.wait_group 1;" ::: "memory");
        } else {
            asm volatile("cp.async.wait_group 0;" ::: "memory");
        }
        __syncthreads();

        const int buf = it & 1;
        const uint32_t base = smBase + (uint32_t)buf * STAGE_B;
        const uint32_t aB = base + (uint32_t)(wm * 32) * (LDA * 2) + laneOff;
        const uint32_t bB = base + TILE_B + (uint32_t)(wn * 64) * (LDA * 2) + laneOff;

        #pragma unroll
        for (int kk = 0; kk < 2; kk++) {
            uint32_t a[2][4], bh[4][4];
            #pragma unroll
            for (int mi = 0; mi < 2; mi++) {
                asm volatile("ldmatrix.sync.aligned.m8n8.x4.shared.b16 {%0,%1,%2,%3}, [%4];"
                    : "=r"(a[mi][0]), "=r"(a[mi][1]), "=r"(a[mi][2]), "=r"(a[mi][3])
                    : "r"(aB + (uint32_t)(mi * 16) * (LDA * 2) + (uint32_t)kk * 32));
            }
            #pragma unroll
            for (int p = 0; p < 4; p++) {
                asm volatile("ldmatrix.sync.aligned.m8n8.x4.shared.b16 {%0,%1,%2,%3}, [%4];"
                    : "=r"(bh[p][0]), "=r"(bh[p][1]), "=r"(bh[p][2]), "=r"(bh[p][3])
                    : "r"(bB + (uint32_t)(p * 16) * (LDA * 2) + (uint32_t)kk * 32));
            }
            #pragma unroll
            for (int mi = 0; mi < 2; mi++) {
                #pragma unroll
                for (int p = 0; p < 4; p++) {
                    asm volatile(
                        "mma.sync.aligned.m16n8k16.row.col.f32.f16.f16.f32 "
                        "{%0,%1,%2,%3},{%4,%5,%6,%7},{%8,%9},{%0,%1,%2,%3};"
                        : "+f"(acc[mi][2*p][0]), "+f"(acc[mi][2*p][1]),
                          "+f"(acc[mi][2*p][2]), "+f"(acc[mi][2*p][3])
                        : "r"(a[mi][0]), "r"(a[mi][1]), "r"(a[mi][2]), "r"(a[mi][3]),
                          "r"(bh[p][0]), "r"(bh[p][2]));
                    asm volatile(
                        "mma.sync.aligned.m16n8k16.row.col.f32.f16.f16.f32 "
                        "{%0,%1,%2,%3},{%4,%5,%6,%7},{%8,%9},{%0,%1,%2,%3};"
                        : "+f"(acc[mi][2*p+1][0]), "+f"(acc[mi][2*p+1][1]),
                          "+f"(acc[mi][2*p+1][2]), "+f"(acc[mi][2*p+1][3])
                        : "r"(a[mi][0]), "r"(a[mi][1]), "r"(a[mi][2]), "r"(a[mi][3]),
                          "r"(bh[p][1]), "r"(bh[p][3]));
                }
            }
        }
        __syncthreads();   // protect buf before it+2 overwrites it
    }

    // epilogue: acc -> g_B
    float* Cn = g_B + (size_t)n * C * C;
    const int mrow0 = tm * 128 + wm * 32 + (lane >> 2);
    const int ncol0 = tn * 128 + wn * 64 + (lane & 3) * 2;
    #pragma unroll
    for (int mi = 0; mi < 2; mi++) {
        #pragma unroll
        for (int ni = 0; ni < 8; ni++) {
            const int r = mrow0 + mi * 16;
            const int cc = ncol0 + ni * 8;
            *(float2*)&Cn[(size_t)r * C + cc]       = make_float2(acc[mi][ni][0], acc[mi][ni][1]);
            *(float2*)&Cn[(size_t)(r + 8) * C + cc] = make_float2(acc[mi][ni][2], acc[mi][ni][3]);
        }
    }
}

// ---------------- kernel 3: fused row-softmax + partial column-sum ----------------
__global__ void k_bsm() {
    __shared__ float cac[8][C];   // 16 KB
    const int n = blockIdx.x, cb = blockIdx.y;
    const int lane = threadIdx.x & 31, wid = threadIdx.x >> 5;

    float wacc[4][4];
    #pragma unroll
    for (int q = 0; q < 4; q++)
        #pragma unroll
        for (int j = 0; j < 4; j++) wacc[q][j] = 0.0f;

    for (int r = wid; r < 64; r += 8) {
        const int row = cb * 64 + r;
        const float* Br = g_B + (size_t)n * C * C + (size_t)row * C;
        const float iz = g_invZ[n * C + row];
        float4 v[4];
        float m = -INFINITY;
        #pragma unroll
        for (int q = 0; q < 4; q++) {
            v[q] = *(const float4*)(Br + q * 128 + lane * 4);
            v[q].x *= iz; v[q].y *= iz; v[q].z *= iz; v[q].w *= iz;
            m = fmaxf(m, fmaxf(fmaxf(v[q].x, v[q].y), fmaxf(v[q].z, v[q].w)));
        }
        #pragma unroll
        for (int o = 16; o; o >>= 1) m = fmaxf(m, __shfl_xor_sync(0xffffffffu, m, o));
        float s = 0.0f;
        #pragma unroll
        for (int q = 0; q < 4; q++) {
            v[q].x = __expf(v[q].x - m); v[q].y = __expf(v[q].y - m);
            v[q].z = __expf(v[q].z - m); v[q].w = __expf(v[q].w - m);
            s += (v[q].x + v[q].y) + (v[q].z + v[q].w);
        }
        #pragma unroll
        for (int o = 16; o; o >>= 1) s += __shfl_xor_sync(0xffffffffu, s, o);
        const float inv = 1.0f / s;
        #pragma unroll
        for (int q = 0; q < 4; q++) {
            wacc[q][0] = fmaf(v[q].x, inv, wacc[q][0]);
            wacc[q][1] = fmaf(v[q].y, inv, wacc[q][1]);
            wacc[q][2] = fmaf(v[q].z, inv, wacc[q][2]);
            wacc[q][3] = fmaf(v[q].w, inv, wacc[q][3]);
        }
    }
    #pragma unroll
    for (int q = 0; q < 4; q++)
        *(float4*)&cac[wid][q * 128 + lane * 4] =
            make_float4(wacc[q][0], wacc[q][1], wacc[q][2], wacc[q][3]);
    __syncthreads();
    #pragma unroll
    for (int h = 0; h < 2; h++) {
        const int col = threadIdx.x + h * 256;
        float s = 0.0f;
        #pragma unroll
        for (int w = 0; w < 8; w++) s += cac[w][col];
        g_wpart[cb][n * C + col] = s;
    }
}

// ---------------- kernel 4: d-split partial output sums ----------------
// grid (7, NB, 4): z = quarter of channels (128 d's). Plain stores to g_opart.
#define S2 (S / 2)   // 1568 half2 per row
__global__ void k_out(float* __restrict__ out) {
    const int n = blockIdx.y;
    const int dq = blockIdx.z;                 // 0..3
    const int s2 = blockIdx.x * 256 + threadIdx.x;
    __shared__ float ws[128];
    if (threadIdx.x < 128) {
        const int d = dq * 128 + threadIdx.x;
        float s = 0.0f;
        #pragma unroll
        for (int w = 0; w < 8; w++) s += g_wpart[w][n * C + d];
        ws[threadIdx.x] = s;
    }
    __syncthreads();
    if (s2 >= S2) return;
    const __half2* fb = (const __half2*)(g_xh + (size_t)n * C * S + (size_t)(dq * 128) * S) + s2;
    float a0 = 0, a1 = 0, b0 = 0, b1 = 0;
    #pragma unroll 4
    for (int d = 0; d < 128; d += 2) {
        float2 f0 = __half22float2(fb[(size_t)d * S2]);
        float2 f1 = __half22float2(fb[(size_t)(d + 1) * S2]);
        a0 = fmaf(ws[d], f0.x, a0);
        a1 = fmaf(ws[d], f0.y, a1);
        b0 = fmaf(ws[d + 1], f1.x, b0);
        b1 = fmaf(ws[d + 1], f1.y, b1);
    }
    float2* o = (float2*)(g_opart[dq] + (size_t)n * S) + s2;
    *o = make_float2(a0 + b0, a1 + b1);
}

// ---------------- kernel 5: combine partials into out ----------------
__global__ void k_comb(float* __restrict__ out) {
    const int i4 = blockIdx.x * 256 + threadIdx.x;   // float4 index, NB*S/4 = 25088
    if (i4 >= NB * S / 4) return;
    float4 v0 = ((const float4*)g_opart[0])[i4];
    float4 v1 = ((const float4*)g_opart[1])[i4];
    float4 v2 = ((const float4*)g_opart[2])[i4];
    float4 v3 = ((const float4*)g_opart[3])[i4];
    float4 o;
    o.x = (v0.x + v1.x) + (v2.x + v3.x);
    o.y = (v0.y + v1.y) + (v2.y + v3.y);
    o.z = (v0.z + v1.z) + (v2.z + v3.z);
    o.w = (v0.w + v1.w) + (v2.w + v3.w);
    ((float4*)out)[i4] = o;
}

extern "C" void kernel_launch(void* const* d_in, const int* in_sizes, int n_in,
                              void* d_out, int out_size) {
    const float* x = (const float*)d_in[0];
    float* out = (float*)d_out;

    cudaFuncSetAttribute(k_gemm_mma, cudaFuncAttributeMaxDynamicSharedMemorySize, SMEM_TOTAL);

    k_rowexp<<<NB * C, 256>>>(x);

    dim3 g2(C / 128, C / 128, NB);   // (4,4,32) = 512 CTAs
    k_gemm_mma<<<g2, 256, SMEM_TOTAL>>>();

    dim3 g3(NB, 8);                  // (32,8) = 256 CTAs
    k_bsm<<<g3, 256>>>();

    dim3 g4((S2 + 255) / 256, NB, 4);  // (7,32,4) = 896 CTAs
    k_out<<<g4, 256>>>(out);

    k_comb<<<(NB * S / 4 + 255) / 256, 256>>>(out);
}